// round 15
// baseline (speedup 1.0000x reference)
#include <cuda_runtime.h>
#include <math.h>

#define NUM_V   6000
#define BATCH   32
#define NBD     (BATCH * 3)   // 96 (batch, dim) pairs
#define CAP_W   128           // compaction capacity (max row nnz; actual ~27)
#define CAP_G   40            // fast-path gather capacity (40*96*4 = 15 KB smem)
#define THREADS 256

// One CTA per Laplacian row v.
// Phase 1: 256 threads stream the 24KB row (LDG.128, evict-first), compact
//          nonzero (w, c) pairs into shared (~13 per row).
// Phase 2a: cooperative gather — all 256 threads fetch the n*96 needed vertex
//           values from L2-resident verts in ONE batch of independent loads.
// Phase 2b: 96 threads do the dot purely out of shared memory.
// Phase 3: reduce over d, sqrt, store.
__global__ void __launch_bounds__(THREADS) lap_norm_kernel(
    const float* __restrict__ L,
    const float* __restrict__ verts,
    float* __restrict__ out)
{
    __shared__ int            s_cnt;
    __shared__ unsigned short s_w[CAP_W];          //   256 B
    __shared__ float          s_c[CAP_W];          //   512 B
    __shared__ float          s_g[CAP_G * NBD];    // 15360 B
    __shared__ float          s_sq[NBD];           //   384 B  -> ~16.5 KB

    const int v   = blockIdx.x;
    const int tid = threadIdx.x;

    if (tid == 0) s_cnt = 0;
    __syncthreads();

    // ---- Phase 1: stream row, compact nonzeros ----
    const float4* row4 = reinterpret_cast<const float4*>(L + (size_t)v * NUM_V);
    const int n4 = NUM_V / 4;  // 1500; rows are 16B-aligned (24000 % 16 == 0)

    #pragma unroll
    for (int k = 0; k < 6; k++) {
        int i4 = k * THREADS + tid;
        if (i4 < n4) {
            float4 c = __ldcs(row4 + i4);   // streaming: L never reused
            if (c.x != 0.f || c.y != 0.f || c.z != 0.f || c.w != 0.f) {
                float vals[4] = {c.x, c.y, c.z, c.w};
                #pragma unroll
                for (int j = 0; j < 4; j++) {
                    if (vals[j] != 0.f) {
                        int slot = atomicAdd(&s_cnt, 1);
                        if (slot < CAP_W) {
                            s_w[slot] = (unsigned short)(i4 * 4 + j);
                            s_c[slot] = vals[j];
                        }
                    }
                }
            }
        }
    }
    __syncthreads();

    const int n = (s_cnt < CAP_W) ? s_cnt : CAP_W;

    if (n <= CAP_G) {
        // ---- Phase 2a: cooperative gather into smem (independent loads) ----
        const int total = n * NBD;
        for (int j = tid; j < total; j += THREADS) {
            int i = j / NBD;           // nonzero index (const divide -> mul/shift)
            int p = j - i * NBD;       // (b,d) pair, 0..95
            int b = p / 3;
            int d = p - b * 3;
            int w = (int)s_w[i];
            s_g[j] = __ldg(verts + ((size_t)b * NUM_V + w) * 3 + d);
        }
        __syncthreads();

        // ---- Phase 2b: dot out of shared (conflict-free) ----
        if (tid < NBD) {
            float acc = 0.f;
            for (int i = 0; i < n; i++)
                acc = fmaf(s_c[i], s_g[i * NBD + tid], acc);
            s_sq[tid] = acc * acc;
        }
    } else {
        // ---- Fallback (n > CAP_G; astronomically unlikely, kept for safety) ----
        if (tid < NBD) {
            int b = tid / 3;
            int d = tid - b * 3;
            const float* vb = verts + (size_t)b * NUM_V * 3 + d;
            float acc = 0.f;
            for (int i = 0; i < n; i++)
                acc = fmaf(s_c[i], __ldg(vb + (int)s_w[i] * 3), acc);
            s_sq[tid] = acc * acc;
        }
    }
    __syncthreads();

    // ---- Phase 3: reduce over d, sqrt, store ----
    if (tid < BATCH) {
        float r = s_sq[tid * 3] + s_sq[tid * 3 + 1] + s_sq[tid * 3 + 2];
        out[(size_t)tid * NUM_V + v] = sqrtf(r);
    }
}

extern "C" void kernel_launch(void* const* d_in, const int* in_sizes, int n_in,
                              void* d_out, int out_size)
{
    const float* a0 = (const float*)d_in[0];
    const float* a1 = (const float*)d_in[1];
    const float *L, *verts;
    if ((long long)in_sizes[0] == (long long)NUM_V * NUM_V) { L = a0; verts = a1; }
    else                                                    { L = a1; verts = a0; }

    lap_norm_kernel<<<NUM_V, THREADS>>>(L, verts, (float*)d_out);
}

// round 16
// speedup vs baseline: 1.0422x; 1.0422x over previous
#include <cuda_runtime.h>
#include <math.h>

#define NUM_V   6000
#define BATCH   32
#define NBD     (BATCH * 3)   // 96 (batch, dim) pairs
#define CAP_W   128           // compaction capacity (actual max row nnz ~27)
#define THREADS 256

// Transposed verts: vT[w][b*3+d]  (6000 x 96 f32 = 2.3 MB, L2-resident)
__device__ float g_vT[NUM_V * NBD];

// Prologue: verts (B,V,3) -> vT (V, B*3). Writes coalesced.
__global__ void __launch_bounds__(THREADS) transpose_kernel(
    const float* __restrict__ verts)
{
    int t = blockIdx.x * THREADS + threadIdx.x;
    if (t < NUM_V * NBD) {
        int w = t / NBD;
        int p = t - w * NBD;       // b*3 + d
        int b = p / 3;
        int d = p - b * 3;
        g_vT[t] = verts[((size_t)b * NUM_V + w) * 3 + d];
    }
}

// One CTA per Laplacian row v.
// Phase 1: 256 threads stream the 24KB row (LDG.128, evict-first), compact
//          nonzero (w, c) pairs into shared (~13 per row).
// Phase 2: 96 threads (one per (b,d)) dot against transposed verts —
//          every vT access is warp-coalesced (3 lines per nonzero, not 96).
// Phase 3: reduce over d, sqrt, store.
__global__ void __launch_bounds__(THREADS) lap_norm_kernel(
    const float* __restrict__ L,
    float* __restrict__ out)
{
    __shared__ int            s_cnt;
    __shared__ unsigned short s_w[CAP_W];   // 256 B
    __shared__ float          s_c[CAP_W];   // 512 B
    __shared__ float          s_sq[NBD];    // 384 B   -> ~1.2 KB total

    const int v   = blockIdx.x;
    const int tid = threadIdx.x;

    if (tid == 0) s_cnt = 0;
    __syncthreads();

    // ---- Phase 1: stream row, compact nonzeros ----
    const float4* row4 = reinterpret_cast<const float4*>(L + (size_t)v * NUM_V);
    const int n4 = NUM_V / 4;  // 1500; rows are 16B-aligned (24000 % 16 == 0)

    #pragma unroll
    for (int k = 0; k < 6; k++) {
        int i4 = k * THREADS + tid;
        if (i4 < n4) {
            float4 c = __ldcs(row4 + i4);   // streaming: L never reused
            if (c.x != 0.f || c.y != 0.f || c.z != 0.f || c.w != 0.f) {
                float vals[4] = {c.x, c.y, c.z, c.w};
                #pragma unroll
                for (int j = 0; j < 4; j++) {
                    if (vals[j] != 0.f) {
                        int slot = atomicAdd(&s_cnt, 1);
                        if (slot < CAP_W) {
                            s_w[slot] = (unsigned short)(i4 * 4 + j);
                            s_c[slot] = vals[j];
                        }
                    }
                }
            }
        }
    }
    __syncthreads();

    const int n = (s_cnt < CAP_W) ? s_cnt : CAP_W;

    // ---- Phase 2: coalesced sparse dot against vT ----
    if (tid < NBD) {
        const float* vt = g_vT + tid;
        float acc = 0.f;
        #pragma unroll 4
        for (int i = 0; i < n; i++) {
            int w = (int)s_w[i];
            acc = fmaf(s_c[i], __ldg(vt + w * NBD), acc);
        }
        s_sq[tid] = acc * acc;
    }
    __syncthreads();

    // ---- Phase 3: reduce over d, sqrt, store ----
    if (tid < BATCH) {
        float r = s_sq[tid * 3] + s_sq[tid * 3 + 1] + s_sq[tid * 3 + 2];
        out[(size_t)tid * NUM_V + v] = sqrtf(r);
    }
}

extern "C" void kernel_launch(void* const* d_in, const int* in_sizes, int n_in,
                              void* d_out, int out_size)
{
    const float* a0 = (const float*)d_in[0];
    const float* a1 = (const float*)d_in[1];
    const float *L, *verts;
    if ((long long)in_sizes[0] == (long long)NUM_V * NUM_V) { L = a0; verts = a1; }
    else                                                    { L = a1; verts = a0; }

    const int t_grid = (NUM_V * NBD + THREADS - 1) / THREADS;  // 2250
    transpose_kernel<<<t_grid, THREADS>>>(verts);
    lap_norm_kernel<<<NUM_V, THREADS>>>(L, (float*)d_out);
}